// round 1
// baseline (speedup 1.0000x reference)
#include <cuda_runtime.h>

#define T_  128
#define B_  2048
#define F_  128
#define H_  64
#define A_  15
#define TB_ (T_*B_)
#define G_  256   // 4*H gates

// Scratch (allocation-free rule: __device__ globals)
__device__ float g_gin[(size_t)TB_ * G_];   // 268 MB: precomputed input-gate preactivations
__device__ float g_z[(size_t)TB_ * H_];     // 67 MB: LSTM hidden outputs per step

__device__ __forceinline__ float fsig(float x) {
    return __fdividef(1.0f, 1.0f + __expf(-x));
}
__device__ __forceinline__ float ftanh(float x) {
    x = fminf(15.0f, fmaxf(-15.0f, x));
    float e = __expf(-2.0f * x);
    return __fdividef(1.0f - e, 1.0f + e);
}

// ---------------------------------------------------------------------------
// Kernel 1: fused MLP encoder + input-gate GEMM.
// 64 rows/block, 256 threads. Thread tile: 8 rows x 2 cols (S1/S2), 8x8 (S3).
// smem floats: xs 8192 | Ws 8192 | h1 4096 | ys 4096 | Wg 256*65=16640  => 41216
// ---------------------------------------------------------------------------
__global__ __launch_bounds__(256, 1)
void k_encode(const float* __restrict__ x,
              const float* __restrict__ W1, const float* __restrict__ b1,
              const float* __restrict__ W2, const float* __restrict__ b2,
              const float* __restrict__ Wih, const float* __restrict__ bih,
              const float* __restrict__ bhh) {
    extern __shared__ float sm[];
    float* xs = sm;            // [64][128]
    float* Ws = sm + 8192;     // W1 [128][64], later W2 [64][64]
    float* h1 = sm + 16384;    // [64][64]
    float* ys = sm + 20480;    // [64][64]
    float* Wg = sm + 24576;    // Wih padded [256][65]
    const int tid  = threadIdx.x;
    const int row0 = blockIdx.x * 64;

    for (int i = tid; i < 64*F_; i += 256) xs[i] = x[(size_t)row0*F_ + i];
    for (int i = tid; i < F_*H_; i += 256) Ws[i] = W1[i];
    for (int i = tid; i < G_*H_; i += 256) Wg[(i>>6)*65 + (i&63)] = Wih[i];
    __syncthreads();

    const int cg = tid & 31;   // column group (strided cols: cg, cg+32)
    const int rg = tid >> 5;   // warp id -> 8 rows each (broadcast-friendly)

    float a0[8], a1[8];
    // ---- S1: h1 = tanh(x @ W1 + b1) ----
    {
        float bb0 = b1[cg], bb1 = b1[cg+32];
        #pragma unroll
        for (int r = 0; r < 8; r++) { a0[r] = bb0; a1[r] = bb1; }
        #pragma unroll 4
        for (int k = 0; k < F_; k++) {
            float w0 = Ws[k*H_ + cg], w1 = Ws[k*H_ + cg + 32];
            #pragma unroll
            for (int r = 0; r < 8; r++) {
                float a = xs[(rg*8+r)*F_ + k];
                a0[r] = fmaf(a, w0, a0[r]); a1[r] = fmaf(a, w1, a1[r]);
            }
        }
        #pragma unroll
        for (int r = 0; r < 8; r++) {
            h1[(rg*8+r)*H_ + cg]      = ftanh(a0[r]);
            h1[(rg*8+r)*H_ + cg + 32] = ftanh(a1[r]);
        }
    }
    __syncthreads();
    for (int i = tid; i < H_*H_; i += 256) Ws[i] = W2[i];
    __syncthreads();
    // ---- S2: y = tanh(h1 @ W2 + b2) ----
    {
        float bb0 = b2[cg], bb1 = b2[cg+32];
        #pragma unroll
        for (int r = 0; r < 8; r++) { a0[r] = bb0; a1[r] = bb1; }
        #pragma unroll 4
        for (int k = 0; k < H_; k++) {
            float w0 = Ws[k*H_ + cg], w1 = Ws[k*H_ + cg + 32];
            #pragma unroll
            for (int r = 0; r < 8; r++) {
                float a = h1[(rg*8+r)*H_ + k];
                a0[r] = fmaf(a, w0, a0[r]); a1[r] = fmaf(a, w1, a1[r]);
            }
        }
        #pragma unroll
        for (int r = 0; r < 8; r++) {
            ys[(rg*8+r)*H_ + cg]      = ftanh(a0[r]);
            ys[(rg*8+r)*H_ + cg + 32] = ftanh(a1[r]);
        }
    }
    __syncthreads();
    // ---- S3: gin = y @ Wih^T + (bih + bhh) ----
    float acc[8][8];
    #pragma unroll
    for (int cc = 0; cc < 8; cc++) {
        int c = cg + 32*cc;
        float bb = bih[c] + bhh[c];
        #pragma unroll
        for (int r = 0; r < 8; r++) acc[r][cc] = bb;
    }
    #pragma unroll 2
    for (int k = 0; k < H_; k++) {
        float w[8];
        #pragma unroll
        for (int cc = 0; cc < 8; cc++) w[cc] = Wg[(cg + 32*cc)*65 + k];
        #pragma unroll
        for (int r = 0; r < 8; r++) {
            float a = ys[(rg*8+r)*H_ + k];
            #pragma unroll
            for (int cc = 0; cc < 8; cc++) acc[r][cc] = fmaf(a, w[cc], acc[r][cc]);
        }
    }
    #pragma unroll
    for (int r = 0; r < 8; r++) {
        float* gp = g_gin + (size_t)(row0 + rg*8 + r) * G_;
        #pragma unroll
        for (int cc = 0; cc < 8; cc++) gp[cg + 32*cc] = acc[r][cc];
    }
}

// ---------------------------------------------------------------------------
// Kernel 2: LSTM recurrence. 16 batch rows/block (independent, no grid sync),
// 128 threads. Per step: gates = gin_tile + h @ Whh^T, then cell update.
// smem floats: Wh 256*65=16640 | hsh 16*64=1024 | gs 16*260=4160 => 21824
// ---------------------------------------------------------------------------
__global__ __launch_bounds__(128, 1)
void k_lstm(const float* __restrict__ done,
            const float* __restrict__ h0, const float* __restrict__ c0,
            const float* __restrict__ Whh, float* __restrict__ out) {
    extern __shared__ float sm[];
    float* Wh  = sm;           // Whh padded [256][65]
    float* hsh = sm + 16640;   // h [16][64]
    float* gs  = sm + 17664;   // gates [16][260]
    const int tid = threadIdx.x;
    const int b0  = blockIdx.x * 16;

    for (int i = tid; i < G_*H_; i += 128) Wh[(i>>6)*65 + (i&63)] = Whh[i];

    // cell-update ownership: thread -> (row rC, units u0..u0+7); c lives in regs
    const int rC = tid >> 3, u0 = (tid & 7) * 8;
    float c_reg[8];
    #pragma unroll
    for (int i = 0; i < 8; i++) {
        c_reg[i] = c0[(b0 + rC)*H_ + u0 + i];
        hsh[rC*H_ + u0 + i] = h0[(b0 + rC)*H_ + u0 + i];
    }
    // matmul ownership: warp wg -> rows wg*4..+3, thread cols cg+32*cc
    const int cg = tid & 31, wg = tid >> 5;
    __syncthreads();

    for (int t = 0; t < T_; t++) {
        // done-mask reset (each thread touches only its own (rC,u) slice)
        float m = 1.0f - done[t*B_ + b0 + rC];
        #pragma unroll
        for (int i = 0; i < 8; i++) {
            c_reg[i] *= m;
            hsh[rC*H_ + u0 + i] *= m;
        }
        __syncthreads();

        // gates = gin + h @ Whh^T
        float acc[4][8];
        const float* gp = g_gin + (size_t)(t*B_ + b0) * G_;
        #pragma unroll
        for (int rr = 0; rr < 4; rr++)
            #pragma unroll
            for (int cc = 0; cc < 8; cc++)
                acc[rr][cc] = gp[(wg*4+rr)*G_ + cg + 32*cc];
        #pragma unroll 2
        for (int k = 0; k < H_; k++) {
            float a[4];
            #pragma unroll
            for (int rr = 0; rr < 4; rr++) a[rr] = hsh[(wg*4+rr)*H_ + k];
            #pragma unroll
            for (int cc = 0; cc < 8; cc++) {
                float w = Wh[(cg + 32*cc)*65 + k];
                #pragma unroll
                for (int rr = 0; rr < 4; rr++) acc[rr][cc] = fmaf(a[rr], w, acc[rr][cc]);
            }
        }
        #pragma unroll
        for (int rr = 0; rr < 4; rr++)
            #pragma unroll
            for (int cc = 0; cc < 8; cc++)
                gs[(wg*4+rr)*260 + cg + 32*cc] = acc[rr][cc];
        __syncthreads();

        // cell update (gate order i,f,g,o)
        float hn[8];
        #pragma unroll
        for (int i = 0; i < 8; i++) {
            int u = u0 + i;
            float gi = gs[rC*260 + u];
            float gf = gs[rC*260 + 64  + u];
            float gc = gs[rC*260 + 128 + u];
            float go = gs[rC*260 + 192 + u];
            float cn = fsig(gf) * c_reg[i] + fsig(gi) * ftanh(gc);
            c_reg[i] = cn;
            hn[i] = fsig(go) * ftanh(cn);
            hsh[rC*H_ + u] = hn[i];
        }
        float* zp = g_z + (size_t)(t*B_ + b0 + rC)*H_ + u0;
        ((float4*)zp)[0] = make_float4(hn[0], hn[1], hn[2], hn[3]);
        ((float4*)zp)[1] = make_float4(hn[4], hn[5], hn[6], hn[7]);
        // next iteration's mask touches only own-thread hsh entries; the
        // loop-top __syncthreads publishes both before the next matmul.
    }

    // epilogue: hT, cT (layout: logits | vf | hT | cT)
    const size_t OH = (size_t)TB_ * 16;       // 15*TB (logits) + TB (vf)
    #pragma unroll
    for (int i = 0; i < 8; i++) {
        out[OH + (size_t)(b0 + rC)*H_ + u0 + i]                    = hsh[rC*H_ + u0 + i];
        out[OH + (size_t)B_*H_ + (size_t)(b0 + rC)*H_ + u0 + i]    = c_reg[i];
    }
}

// ---------------------------------------------------------------------------
// Kernel 3: actor/critic heads. 128 rows/block, 1 row/thread.
// Wa and Wc fused into a [64][16] weight tile (cols 0..14 = Wa, col 15 = Wc).
// ---------------------------------------------------------------------------
__global__ __launch_bounds__(128)
void k_heads(const float* __restrict__ Wa, const float* __restrict__ ba,
             const float* __restrict__ Wc, const float* __restrict__ bc,
             float* __restrict__ out) {
    __shared__ float ws[H_*16];
    __shared__ float zs[128*65];
    const int tid  = threadIdx.x;
    const int row0 = blockIdx.x * 128;

    for (int i = tid; i < 128*H_; i += 128) zs[(i>>6)*65 + (i&63)] = g_z[(size_t)row0*H_ + i];
    for (int i = tid; i < H_*16; i += 128) {
        int k = i >> 4, j = i & 15;
        ws[i] = (j < 15) ? Wa[k*A_ + j] : Wc[k];
    }
    __syncthreads();

    float acc[16];
    #pragma unroll
    for (int j = 0; j < 15; j++) acc[j] = ba[j];
    acc[15] = bc[0];
    #pragma unroll 4
    for (int k = 0; k < H_; k++) {
        float a = zs[tid*65 + k];
        #pragma unroll
        for (int j = 0; j < 16; j++) acc[j] = fmaf(a, ws[k*16 + j], acc[j]);
    }
    const size_t r = (size_t)row0 + tid;
    #pragma unroll
    for (int j = 0; j < 15; j++) out[r*A_ + j] = acc[j];
    out[(size_t)TB_*A_ + r] = acc[15];
}

// ---------------------------------------------------------------------------
extern "C" void kernel_launch(void* const* d_in, const int* in_sizes, int n_in,
                              void* d_out, int out_size) {
    const float* x    = (const float*)d_in[0];
    const float* done = (const float*)d_in[1];
    const float* h0   = (const float*)d_in[2];
    const float* c0   = (const float*)d_in[3];
    const float* W1   = (const float*)d_in[4];
    const float* b1   = (const float*)d_in[5];
    const float* W2   = (const float*)d_in[6];
    const float* b2   = (const float*)d_in[7];
    const float* Wih  = (const float*)d_in[8];
    const float* bih  = (const float*)d_in[9];
    const float* Whh  = (const float*)d_in[10];
    const float* bhh  = (const float*)d_in[11];
    const float* Wa   = (const float*)d_in[12];
    const float* ba   = (const float*)d_in[13];
    const float* Wc   = (const float*)d_in[14];
    const float* bc   = (const float*)d_in[15];
    float* out = (float*)d_out;

    cudaFuncSetAttribute(k_encode, cudaFuncAttributeMaxDynamicSharedMemorySize, 41216*4);
    cudaFuncSetAttribute(k_lstm,   cudaFuncAttributeMaxDynamicSharedMemorySize, 21824*4);

    k_encode<<<TB_/64, 256, 41216*4>>>(x, W1, b1, W2, b2, Wih, bih, bhh);
    k_lstm<<<B_/16, 128, 21824*4>>>(done, h0, c0, Whh, out);
    k_heads<<<TB_/128, 128>>>(Wa, ba, Wc, bc, out);
}